// round 11
// baseline (speedup 1.0000x reference)
#include <cuda_runtime.h>
#include <cuda_fp16.h>
#include <cstdint>

// ---------------------------------------------------------------------------
// TalkingHeadAttention: B=4, N=1024, C=768, H=12, d=64
// fp16-split (3-term) mma.sync GEMMs + fp32 softmax/mix.
// Round 11: single-barrier 4-stage cp.async pipeline (BK=32, SW64 tiles) for
// K1/K2/K5; K4 rebuilt at BM=64 with 2 CTAs/SM.
// d_out layout: [ out (4096*768) | attn (4*12*1024*1024) ]
// ---------------------------------------------------------------------------

#define BATCH 4
#define SEQ   1024
#define CDIM  768
#define HEADS 12
#define HDIM  64
#define QKVC  2304
#define TOKS  4096
#define OUT_ELEMS (TOKS * CDIM)

__device__ float  g_logits[(size_t)BATCH * HEADS * SEQ * SEQ]; // 201 MB
__device__ __half g_x_hi[TOKS * CDIM],      g_x_lo[TOKS * CDIM];
__device__ __half g_qkv_hi[TOKS * QKVC],    g_qkv_lo[TOKS * QKVC];
__device__ __half g_wqkvt_hi[QKVC * CDIM],  g_wqkvt_lo[QKVC * CDIM];
__device__ __half g_wprojt_hi[CDIM * CDIM], g_wprojt_lo[CDIM * CDIM];
__device__ __half g_vt_hi[BATCH * HEADS * HDIM * SEQ], g_vt_lo[BATCH * HEADS * HDIM * SEQ];
__device__ __half g_ctx_hi[TOKS * CDIM],    g_ctx_lo[TOKS * CDIM];

// ------------------------------ asm helpers --------------------------------
__device__ __forceinline__ uint32_t smem_to_u32(const void* p) {
    uint32_t a;
    asm("{ .reg .u64 t; cvta.to.shared.u64 t, %1; cvt.u32.u64 %0, t; }" : "=r"(a) : "l"(p));
    return a;
}
#define LDSM4(d0, d1, d2, d3, a) \
    asm volatile("ldmatrix.sync.aligned.m8n8.x4.shared.b16 {%0,%1,%2,%3}, [%4];" \
                 : "=r"(d0), "=r"(d1), "=r"(d2), "=r"(d3) : "r"(a))
#define MMA16816(c, a, b) \
    asm volatile("mma.sync.aligned.m16n8k16.row.col.f32.f16.f16.f32 " \
                 "{%0,%1,%2,%3}, {%4,%5,%6,%7}, {%8,%9}, {%0,%1,%2,%3};" \
                 : "+f"((c)[0]), "+f"((c)[1]), "+f"((c)[2]), "+f"((c)[3]) \
                 : "r"((a)[0]), "r"((a)[1]), "r"((a)[2]), "r"((a)[3]), \
                   "r"((b)[0]), "r"((b)[1]))
#define CP_ASYNC16(sm, gp) \
    asm volatile("cp.async.cg.shared.global [%0], [%1], 16;" :: "r"(sm), "l"(gp))
#define CP_COMMIT() asm volatile("cp.async.commit_group;" ::: "memory")

// split fp32x4 -> fp16 hi/lo, store 8B each to SW128-swizzled smem (K4 A path)
__device__ __forceinline__ void split_store_h(float4 v, char* hi, char* lo, int off) {
    const int sw = off ^ ((off >> 3) & 0x70);
    __half2 h01 = __floats2half2_rn(v.x, v.y);
    __half2 h23 = __floats2half2_rn(v.z, v.w);
    *(uint2*)(hi + sw) = make_uint2(*(uint32_t*)&h01, *(uint32_t*)&h23);
    float2 f01 = __half22float2(h01), f23 = __half22float2(h23);
    __half2 l01 = __floats2half2_rn(v.x - f01.x, v.y - f01.y);
    __half2 l23 = __floats2half2_rn(v.z - f23.x, v.w - f23.y);
    *(uint2*)(lo + sw) = make_uint2(*(uint32_t*)&l01, *(uint32_t*)&l23);
}

// ---------------------------------------------------------------------------
// Pipelined GEMM (MODE 0=K1, 1=K2, 3=K5): D[M,N] = A[M,K].B[N,K]^T.
// BM=128, BN=64, BK=32, 4-stage single-barrier cp.async ring, SW64 tiles.
// All operands pre-split fp16 hi/lo in gmem.
// ---------------------------------------------------------------------------
template <int MODE>
__global__ __launch_bounds__(256, 2)
void tc_gemm(const __half* __restrict__ Ah_gp, const __half* __restrict__ Al_gp,
             const __half* __restrict__ Bh_gp, const __half* __restrict__ Bl_gp,
             const float* __restrict__ bias, void* Ca, void* Cb)
{
    constexpr bool C_SPLIT = (MODE == 0);
    constexpr int BN    = 64;
    constexpr int K_TOT = (MODE == 1) ? 64 : 768;
    constexpr int LDA   = (MODE == 0) ? CDIM : (MODE == 1) ? QKVC : CDIM;
    constexpr int LDB   = (MODE == 1) ? QKVC : CDIM;
    constexpr int LDC   = (MODE == 0) ? QKVC : (MODE == 1) ? SEQ : CDIM;
    constexpr int NITER = K_TOT / 32;
    constexpr int S     = 4;
    constexpr int WAITN = (S - 2 < NITER - 1) ? S - 2 : NITER - 1;
    constexpr int NPRO  = (S - 1 < NITER) ? S - 1 : NITER;
    constexpr int WM    = 2;
    constexpr int OFF_AL = 8192;
    constexpr int OFF_BH = 16384;
    constexpr int OFF_BL = 20480;
    constexpr int STAGE  = 24576;

    extern __shared__ char smem[];
    const uint32_t smem_base = smem_to_u32(smem);
    const int tid  = threadIdx.x;
    const int warp = tid >> 5;
    const int lane = tid & 31;
    const int wmBase = (warp >> 1) * 32;
    const int wnBase = (warp & 1) * 32;

    const int row0 = blockIdx.y * 128;
    const int col0 = blockIdx.x * BN;
    const int z = blockIdx.z;

    size_t aOff = 0, bOff = 0, cOff = 0;
    if (MODE == 1) {
        const int b = z / HEADS, h = z % HEADS;
        aOff = (size_t)b * SEQ * QKVC + (size_t)h * HDIM;
        bOff = aOff + CDIM;
        cOff = (size_t)z * SEQ * SEQ;
    }
    const __half* Ah_g = Ah_gp + aOff;
    const __half* Al_g = Al_gp + aOff;
    const __half* Bh_g = Bh_gp + bOff;
    const __half* Bl_g = Bl_gp + bOff;
    float*  Cf = (float*)Ca + cOff;
    __half* Ch = (__half*)Ca + cOff;
    __half* Cl = (__half*)Cb + cOff;

    float acc[WM][4][4];
#pragma unroll
    for (int i = 0; i < WM; i++)
#pragma unroll
        for (int j = 0; j < 4; j++)
#pragma unroll
            for (int e = 0; e < 4; e++) acc[i][j][e] = 0.0f;

    // stage tiles: 64B rows, SW64 swizzle (off ^ ((off>>3)&0x30))
    auto issue_stage = [&](int s, int k0) {
        const uint32_t sb = smem_base + s * STAGE;
        // A hi/lo: 128 rows x 4 chunks = 512 -> 2 per thread each
#pragma unroll
        for (int l = 0; l < 2; l++) {
            const int c = tid + l * 256;
            const int row = c >> 2, cc = c & 3;
            int off = row * 64 + cc * 16;
            off ^= (off >> 3) & 0x30;
            CP_ASYNC16(sb + off,          Ah_g + (size_t)(row0 + row) * LDA + k0 + cc * 8);
            CP_ASYNC16(sb + OFF_AL + off, Al_g + (size_t)(row0 + row) * LDA + k0 + cc * 8);
        }
        // B hi/lo: 64 rows x 4 chunks = 256 -> 1 per thread each
        {
            const int row = tid >> 2, cc = tid & 3;
            int off = row * 64 + cc * 16;
            off ^= (off >> 3) & 0x30;
            CP_ASYNC16(sb + OFF_BH + off, Bh_g + (size_t)(col0 + row) * LDB + k0 + cc * 8);
            CP_ASYNC16(sb + OFF_BL + off, Bl_g + (size_t)(col0 + row) * LDB + k0 + cc * 8);
        }
    };
    auto compute = [&](int s) {
        const uint32_t sb = smem_base + s * STAGE;
        const int r = lane & 7, g = lane >> 3;
#pragma unroll
        for (int kk = 0; kk < 2; kk++) {
            uint32_t ah[WM][4], al[WM][4];
#pragma unroll
            for (int i = 0; i < WM; i++) {
                const int row = wmBase + i * 16 + (g & 1) * 8 + r;
                int off = row * 64 + kk * 32 + (g >> 1) * 16;
                off ^= (off >> 3) & 0x30;
                LDSM4(ah[i][0], ah[i][1], ah[i][2], ah[i][3], sb + off);
                LDSM4(al[i][0], al[i][1], al[i][2], al[i][3], sb + OFF_AL + off);
            }
            uint32_t bh[4][2], bl[4][2];
#pragma unroll
            for (int jp = 0; jp < 2; jp++) {
                const int n = wnBase + jp * 16 + (g >> 1) * 8 + r;
                int off = n * 64 + kk * 32 + (g & 1) * 16;
                off ^= (off >> 3) & 0x30;
                LDSM4(bh[2 * jp][0], bh[2 * jp][1], bh[2 * jp + 1][0], bh[2 * jp + 1][1],
                      sb + OFF_BH + off);
                LDSM4(bl[2 * jp][0], bl[2 * jp][1], bl[2 * jp + 1][0], bl[2 * jp + 1][1],
                      sb + OFF_BL + off);
            }
#pragma unroll
            for (int i = 0; i < WM; i++)
#pragma unroll
                for (int j = 0; j < 4; j++) {
                    MMA16816(acc[i][j], ah[i], bh[j]);
                    MMA16816(acc[i][j], ah[i], bl[j]);
                    MMA16816(acc[i][j], al[i], bh[j]);
                }
        }
    };

    // prologue: fill S-1 stages (or all NITER if fewer)
#pragma unroll
    for (int s = 0; s < NPRO; s++) {
        issue_stage(s, s * 32);
        CP_COMMIT();
    }

    for (int it = 0; it < NITER; it++) {
        asm volatile("cp.async.wait_group %0;" :: "n"(WAITN) : "memory");
        __syncthreads();
        compute(it % S);
        const int nf = it + S - 1;
        if (nf < NITER) issue_stage(nf % S, nf * 32);
        CP_COMMIT();
    }

    // epilogue
    const int qr = lane >> 2;
    const int qc = (lane & 3) * 2;
#pragma unroll
    for (int i = 0; i < WM; i++) {
#pragma unroll
        for (int j = 0; j < 4; j++) {
            const int gr = row0 + wmBase + i * 16 + qr;
            const int gc = col0 + wnBase + j * 8 + qc;
            float v0 = acc[i][j][0], v1 = acc[i][j][1];
            float v2 = acc[i][j][2], v3 = acc[i][j][3];
            if (MODE == 0 || MODE == 3) {
                const float b0 = bias[gc], b1 = bias[gc + 1];
                v0 += b0; v1 += b1; v2 += b0; v3 += b1;
            }
            if (MODE == 0) {
                if (gc < CDIM)     { v0 *= 0.125f; v2 *= 0.125f; }
                if (gc + 1 < CDIM) { v1 *= 0.125f; v3 *= 0.125f; }
            }
            if (C_SPLIT) {
                __half2 h0 = __floats2half2_rn(v0, v1);
                __half2 h1 = __floats2half2_rn(v2, v3);
                *(__half2*)&Ch[(size_t)gr * LDC + gc]       = h0;
                *(__half2*)&Ch[(size_t)(gr + 8) * LDC + gc] = h1;
                float2 f0 = __half22float2(h0), f1 = __half22float2(h1);
                *(__half2*)&Cl[(size_t)gr * LDC + gc]       = __floats2half2_rn(v0 - f0.x, v1 - f0.y);
                *(__half2*)&Cl[(size_t)(gr + 8) * LDC + gc] = __floats2half2_rn(v2 - f1.x, v3 - f1.y);
            } else {
                *(float2*)&Cf[(size_t)gr * LDC + gc]       = make_float2(v0, v1);
                *(float2*)&Cf[(size_t)(gr + 8) * LDC + gc] = make_float2(v2, v3);
            }
        }
    }
}

// ---------------------------------------------------------------------------
// K4: ctx = attn @ vt^T per (b,h). BM=64, BN=64, BK=64, 2-stage, 2 CTAs/SM.
// A (fp32 attn) runtime-split; B (vt hi/lo) via cp.async. SW128 tiles.
// ---------------------------------------------------------------------------
__global__ __launch_bounds__(256, 2)
void tc_gemm_av(const float* __restrict__ Ag,
                const __half* __restrict__ Bh_gp, const __half* __restrict__ Bl_gp,
                __half* __restrict__ Chp, __half* __restrict__ Clp)
{
    constexpr int NITER = SEQ / 64;   // 16
    constexpr int AREG  = 4;
    constexpr int OFF_AL = 8192;
    constexpr int OFF_BH = 16384;
    constexpr int OFF_BL = 24576;
    constexpr int STAGE  = 32768;

    extern __shared__ char smem[];
    const uint32_t smem_base = smem_to_u32(smem);
    const int tid  = threadIdx.x;
    const int warp = tid >> 5;
    const int lane = tid & 31;
    const int wmBase = (warp >> 1) * 16;
    const int wnBase = (warp & 1) * 32;

    const int row0 = blockIdx.y * 64;
    const int z = blockIdx.z;
    const float*  Af   = Ag + (size_t)z * SEQ * SEQ;
    const __half* Bh_g = Bh_gp + (size_t)z * HDIM * SEQ;
    const __half* Bl_g = Bl_gp + (size_t)z * HDIM * SEQ;
    const size_t cOff = (size_t)(z / HEADS) * SEQ * CDIM + (size_t)(z % HEADS) * HDIM;
    __half* Ch = Chp + cOff;
    __half* Cl = Clp + cOff;

    float acc[4][4];
#pragma unroll
    for (int j = 0; j < 4; j++)
#pragma unroll
        for (int e = 0; e < 4; e++) acc[j][e] = 0.0f;

    float4 aRf[AREG];

    auto issue_B = [&](int p, int k0) {
        const uint32_t sb = smem_base + p * STAGE;
#pragma unroll
        for (int l = 0; l < 2; l++) {
            const int c = tid + l * 256;
            const int row = c >> 3, cc = c & 7;
            int off = row * 128 + cc * 16;
            off ^= (off >> 3) & 0x70;
            CP_ASYNC16(sb + OFF_BH + off, Bh_g + (size_t)row * SEQ + k0 + cc * 8);
            CP_ASYNC16(sb + OFF_BL + off, Bl_g + (size_t)row * SEQ + k0 + cc * 8);
        }
    };
    auto loadA = [&](int k0) {
#pragma unroll
        for (int l = 0; l < AREG; l++) {
            const int g = tid + l * 256;
            aRf[l] = *(const float4*)&Af[(size_t)(row0 + (g >> 4)) * SEQ + k0 + (g & 15) * 4];
        }
    };
    auto storeA = [&](int p) {
        char* base = smem + p * STAGE;
#pragma unroll
        for (int l = 0; l < AREG; l++) {
            const int g = tid + l * 256;
            split_store_h(aRf[l], base, base + OFF_AL, (g >> 4) * 128 + (g & 15) * 8);
        }
    };
    auto compute = [&](int p, int kkBeg, int kkEnd) {
        const uint32_t sb = smem_base + p * STAGE;
        const int r = lane & 7, g = lane >> 3;
        for (int kk = kkBeg; kk < kkEnd; kk++) {
            uint32_t ah[4], al[4];
            {
                const int row = wmBase + (g & 1) * 8 + r;
                int off = row * 128 + kk * 32 + (g >> 1) * 16;
                off ^= (off >> 3) & 0x70;
                LDSM4(ah[0], ah[1], ah[2], ah[3], sb + off);
                LDSM4(al[0], al[1], al[2], al[3], sb + OFF_AL + off);
            }
            uint32_t bh[4][2], bl[4][2];
#pragma unroll
            for (int jp = 0; jp < 2; jp++) {
                const int n = wnBase + jp * 16 + (g >> 1) * 8 + r;
                int off = n * 128 + kk * 32 + (g & 1) * 16;
                off ^= (off >> 3) & 0x70;
                LDSM4(bh[2 * jp][0], bh[2 * jp][1], bh[2 * jp + 1][0], bh[2 * jp + 1][1],
                      sb + OFF_BH + off);
                LDSM4(bl[2 * jp][0], bl[2 * jp][1], bl[2 * jp + 1][0], bl[2 * jp + 1][1],
                      sb + OFF_BL + off);
            }
#pragma unroll
            for (int j = 0; j < 4; j++) {
                MMA16816(acc[j], ah, bh[j]);
                MMA16816(acc[j], ah, bl[j]);
                MMA16816(acc[j], al, bh[j]);
            }
        }
    };

    loadA(0);
    issue_B(0, 0);
    CP_COMMIT();
    storeA(0);

    for (int it = 0; it < NITER; it++) {
        const int p = it & 1;
        const bool more = (it + 1 < NITER);
        if (more) {
            issue_B(p ^ 1, (it + 1) * 64);
            CP_COMMIT();
            loadA((it + 1) * 64);
        }
        if (more) asm volatile("cp.async.wait_group 1;" ::: "memory");
        else      asm volatile("cp.async.wait_group 0;" ::: "memory");
        __syncthreads();
        compute(p, 0, 2);
        if (more) storeA(p ^ 1);
        compute(p, 2, 4);
        __syncthreads();
    }

    const int qr = lane >> 2;
    const int qc = (lane & 3) * 2;
#pragma unroll
    for (int j = 0; j < 4; j++) {
        const int gr = row0 + wmBase + qr;
        const int gc = (warp & 1) * 32 + j * 8 + qc;
        float v0 = acc[j][0], v1 = acc[j][1], v2 = acc[j][2], v3 = acc[j][3];
        __half2 h0 = __floats2half2_rn(v0, v1);
        __half2 h1 = __floats2half2_rn(v2, v3);
        *(__half2*)&Ch[(size_t)gr * CDIM + gc]       = h0;
        *(__half2*)&Ch[(size_t)(gr + 8) * CDIM + gc] = h1;
        float2 f0 = __half22float2(h0), f1 = __half22float2(h1);
        *(__half2*)&Cl[(size_t)gr * CDIM + gc]       = __floats2half2_rn(v0 - f0.x, v1 - f0.y);
        *(__half2*)&Cl[(size_t)(gr + 8) * CDIM + gc] = __floats2half2_rn(v2 - f1.x, v3 - f1.y);
    }
}

// ---------------------------------------------------------------------------
// P0: presplit fp32 -> fp16 hi/lo
// ---------------------------------------------------------------------------
__global__ void presplit(const float* __restrict__ in,
                         __half* __restrict__ hi, __half* __restrict__ lo, int n4)
{
    const int i = blockIdx.x * blockDim.x + threadIdx.x;
    if (i >= n4) return;
    float4 v = ((const float4*)in)[i];
    __half2 h01 = __floats2half2_rn(v.x, v.y);
    __half2 h23 = __floats2half2_rn(v.z, v.w);
    ((__half2*)hi)[2 * i]     = h01;
    ((__half2*)hi)[2 * i + 1] = h23;
    float2 f01 = __half22float2(h01), f23 = __half22float2(h23);
    ((__half2*)lo)[2 * i]     = __floats2half2_rn(v.x - f01.x, v.y - f01.y);
    ((__half2*)lo)[2 * i + 1] = __floats2half2_rn(v.z - f23.x, v.w - f23.y);
}

// ---------------------------------------------------------------------------
// P1/P2: transpose fp32 [rows][cols] -> fp16 hi/lo [cols][rows]
// ---------------------------------------------------------------------------
__global__ void transpose_split(const float* __restrict__ in,
                                __half* __restrict__ hi, __half* __restrict__ lo,
                                int rows, int cols)
{
    __shared__ float t[32][33];
    const int x = blockIdx.x * 32 + threadIdx.x;
    const int y0 = blockIdx.y * 32;
#pragma unroll
    for (int j = threadIdx.y; j < 32; j += 8)
        t[j][threadIdx.x] = in[(size_t)(y0 + j) * cols + x];
    __syncthreads();
    const int x2 = y0 + threadIdx.x;
    const int y2 = blockIdx.x * 32;
#pragma unroll
    for (int j = threadIdx.y; j < 32; j += 8) {
        const float v = t[threadIdx.x][j];
        const __half h = __float2half_rn(v);
        hi[(size_t)(y2 + j) * rows + x2] = h;
        lo[(size_t)(y2 + j) * rows + x2] = __float2half_rn(v - __half2float(h));
    }
}

// ---------------------------------------------------------------------------
// P3: transpose v slice of qkv_hi/lo -> vt_hi/lo [bh][d][m]
// ---------------------------------------------------------------------------
__global__ void vt_split(const __half* __restrict__ qh, const __half* __restrict__ ql,
                         __half* __restrict__ vh, __half* __restrict__ vl)
{
    __shared__ __half th[32][33], tl[32][33];
    const int z = blockIdx.z;
    const int b = z / HEADS, h = z % HEADS;
    const size_t inBase = (size_t)b * SEQ * QKVC + 2 * CDIM + (size_t)h * HDIM;
    const int m0 = blockIdx.x * 32, d0 = blockIdx.y * 32;
#pragma unroll
    for (int j = threadIdx.y; j < 32; j += 8) {
        const size_t idx = inBase + (size_t)(m0 + j) * QKVC + d0 + threadIdx.x;
        th[j][threadIdx.x] = qh[idx];
        tl[j][threadIdx.x] = ql[idx];
    }
    __syncthreads();
    const size_t outBase = (size_t)z * HDIM * SEQ;
#pragma unroll
    for (int j = threadIdx.y; j < 32; j += 8) {
        const size_t idx = outBase + (size_t)(d0 + j) * SEQ + m0 + threadIdx.x;
        vh[idx] = th[threadIdx.x][j];
        vl[idx] = tl[threadIdx.x][j];
    }
}

// ---------------------------------------------------------------------------
// K3 (fp32, register-resident): per (b,n): mix1 -> softmax -> mix2 -> attn
// ---------------------------------------------------------------------------
__global__ __launch_bounds__(256)
void mix_softmax_kernel(const float* __restrict__ logits,
                        const float* __restrict__ W_l, const float* __restrict__ b_l,
                        const float* __restrict__ W_w, const float* __restrict__ b_w,
                        float* __restrict__ attn_out)
{
    __shared__ float swl[HEADS * HEADS], sww[HEADS * HEADS];
    __shared__ float sbl[HEADS], sbw[HEADS];
    __shared__ float red[HEADS][8];

    const int tid  = threadIdx.x;
    const int lane = tid & 31;
    const int warp = tid >> 5;
    const int bn = blockIdx.x;
    const int b = bn >> 10;
    const int n = bn & (SEQ - 1);

    if (tid < HEADS * HEADS) { swl[tid] = W_l[tid]; sww[tid] = W_w[tid]; }
    if (tid < HEADS) { sbl[tid] = b_l[tid]; sbw[tid] = b_w[tid]; }
    __syncthreads();

    const float* lb = logits + ((size_t)b * HEADS * SEQ + n) * SEQ + tid * 4;
    float4 l[HEADS];
#pragma unroll
    for (int h = 0; h < HEADS; h++)
        l[h] = *(const float4*)&lb[(size_t)h * SEQ * SEQ];

    float4 m1[HEADS];
#pragma unroll
    for (int k = 0; k < HEADS; k++) {
        float bk = sbl[k];
        float4 a = make_float4(bk, bk, bk, bk);
#pragma unroll
        for (int h = 0; h < HEADS; h++) {
            const float w = swl[h * HEADS + k];
            a.x = fmaf(l[h].x, w, a.x);
            a.y = fmaf(l[h].y, w, a.y);
            a.z = fmaf(l[h].z, w, a.z);
            a.w = fmaf(l[h].w, w, a.w);
        }
        m1[k] = a;
    }

    float rowmax[HEADS];
#pragma unroll
    for (int k = 0; k < HEADS; k++) {
        float v = fmaxf(fmaxf(m1[k].x, m1[k].y), fmaxf(m1[k].z, m1[k].w));
#pragma unroll
        for (int o = 16; o > 0; o >>= 1) v = fmaxf(v, __shfl_xor_sync(0xffffffff, v, o));
        if (lane == 0) red[k][warp] = v;
    }
    __syncthreads();
#pragma unroll
    for (int k = 0; k < HEADS; k++) {
        float v = red[k][0];
#pragma unroll
        for (int w = 1; w < 8; w++) v = fmaxf(v, red[k][w]);
        rowmax[k] = v;
    }
    __syncthreads();

    float inv[HEADS];
#pragma unroll
    for (int k = 0; k < HEADS; k++) {
        m1[k].x = __expf(m1[k].x - rowmax[k]);
        m1[k].y = __expf(m1[k].y - rowmax[k]);
        m1[k].z = __expf(m1[k].z - rowmax[k]);
        m1[k].w = __expf(m1[k].w - rowmax[k]);
        float s = (m1[k].x + m1[k].y) + (m1[k].z + m1[k].w);
#pragma unroll
        for (int o = 16; o > 0; o >>= 1) s += __shfl_xor_sync(0xffffffff, s, o);
        if (lane == 0) red[k][warp] = s;
    }
    __syncthreads();
#pragma unroll
    for (int k = 0; k < HEADS; k++) {
        float s = red[k][0];
#pragma unroll
        for (int w = 1; w < 8; w++) s += red[k][w];
        inv[k] = 1.0f / s;
    }

#pragma unroll
    for (int h = 0; h < HEADS; h++) {
        m1[h].x *= inv[h]; m1[h].y *= inv[h];
        m1[h].z *= inv[h]; m1[h].w *= inv[h];
    }

    float* ob = attn_out + ((size_t)b * HEADS * SEQ + n) * SEQ + tid * 4;
#pragma unroll
    for (int k = 0; k < HEADS; k++) {
        float bk = sbw[k];
        float4 a = make_float4(bk, bk, bk, bk);
#pragma unroll
        for (int h = 0; h < HEADS; h++) {
            const float w = sww[h * HEADS + k];
            a.x = fmaf(m1[h].x, w, a.x);
            a.y = fmaf(m1[h].y, w, a.y);
            a.z = fmaf(m1[h].z, w, a.z);
            a.w = fmaf(m1[h].w, w, a.w);
        }
        *(float4*)&ob[(size_t)k * SEQ * SEQ] = a;
    }
}

// ---------------------------------------------------------------------------
extern "C" void kernel_launch(void* const* d_in, const int* in_sizes, int n_in,
                              void* d_out, int out_size)
{
    const float* x      = (const float*)d_in[0];
    const float* W_qkv  = (const float*)d_in[1];
    const float* b_qkv  = (const float*)d_in[2];
    const float* W_l    = (const float*)d_in[3];
    const float* b_l    = (const float*)d_in[4];
    const float* W_w    = (const float*)d_in[5];
    const float* b_w    = (const float*)d_in[6];
    const float* W_proj = (const float*)d_in[7];
    const float* b_proj = (const float*)d_in[8];

    float* out  = (float*)d_out;
    float* attn = out + OUT_ELEMS;

    float* logits_p;
    __half *xh, *xl, *qh, *ql, *wqh, *wql, *wph, *wpl, *vh, *vl, *ch, *cl;
    cudaGetSymbolAddress((void**)&logits_p, g_logits);
    cudaGetSymbolAddress((void**)&xh, g_x_hi);      cudaGetSymbolAddress((void**)&xl, g_x_lo);
    cudaGetSymbolAddress((void**)&qh, g_qkv_hi);    cudaGetSymbolAddress((void**)&ql, g_qkv_lo);
    cudaGetSymbolAddress((void**)&wqh, g_wqkvt_hi); cudaGetSymbolAddress((void**)&wql, g_wqkvt_lo);
    cudaGetSymbolAddress((void**)&wph, g_wprojt_hi);cudaGetSymbolAddress((void**)&wpl, g_wprojt_lo);
    cudaGetSymbolAddress((void**)&vh, g_vt_hi);     cudaGetSymbolAddress((void**)&vl, g_vt_lo);
    cudaGetSymbolAddress((void**)&ch, g_ctx_hi);    cudaGetSymbolAddress((void**)&cl, g_ctx_lo);

    const int smemPipe = 4 * 24576;   // 98304 (modes 0/3)
    const int smemK2   = 2 * 24576;   // 49152 (NITER=2 uses stages 0/1 only)
    const int smemK4   = 2 * 32768;   // 65536
    cudaFuncSetAttribute(tc_gemm<0>, cudaFuncAttributeMaxDynamicSharedMemorySize, smemPipe);
    cudaFuncSetAttribute(tc_gemm<1>, cudaFuncAttributeMaxDynamicSharedMemorySize, smemK2);
    cudaFuncSetAttribute(tc_gemm<3>, cudaFuncAttributeMaxDynamicSharedMemorySize, smemPipe);
    cudaFuncSetAttribute(tc_gemm_av, cudaFuncAttributeMaxDynamicSharedMemorySize, smemK4);

    // P0: presplit x
    presplit<<<(TOKS * CDIM / 4 + 255) / 256, 256>>>(x, xh, xl, TOKS * CDIM / 4);

    // P1/P2: transpose+split weights -> [N][K] fp16 hi/lo
    transpose_split<<<dim3(QKVC / 32, CDIM / 32), dim3(32, 8)>>>(W_qkv, wqh, wql, CDIM, QKVC);
    transpose_split<<<dim3(CDIM / 32, CDIM / 32), dim3(32, 8)>>>(W_proj, wph, wpl, CDIM, CDIM);

    // K1: qkv = x @ W_qkv^T' + b (q scaled) -> qkv_hi/lo
    tc_gemm<0><<<dim3(QKVC / 64, TOKS / 128, 1), 256, smemPipe>>>(
        xh, xl, wqh, wql, b_qkv, qh, ql);

    // P3: v transpose -> vt_hi/lo [bh][d][m]
    vt_split<<<dim3(SEQ / 32, HDIM / 32, BATCH * HEADS), dim3(32, 8)>>>(qh, ql, vh, vl);

    // K2: logits = q @ k^T per (b,h)  (fp32 out)
    tc_gemm<1><<<dim3(SEQ / 64, SEQ / 128, BATCH * HEADS), 256, smemK2>>>(
        qh, ql, qh, ql, nullptr, logits_p, nullptr);

    // K3: mix -> softmax -> mix -> attn output (fp32)
    mix_softmax_kernel<<<TOKS, 256>>>(logits_p, W_l, b_l, W_w, b_w, attn);

    // K4: ctx = attn @ vt^T per (b,h) -> ctx_hi/lo
    tc_gemm_av<<<dim3(1, SEQ / 64, BATCH * HEADS), 256, smemK4>>>(
        attn, vh, vl, ch, cl);

    // K5: out = ctx @ W_proj^T' + b (fp32 out)
    tc_gemm<3><<<dim3(CDIM / 64, TOKS / 128, 1), 256, smemPipe>>>(
        ch, cl, wph, wpl, b_proj, out, nullptr);
}

// round 13
// speedup vs baseline: 1.0006x; 1.0006x over previous
#include <cuda_runtime.h>
#include <cuda_fp16.h>
#include <cstdint>

// ---------------------------------------------------------------------------
// TalkingHeadAttention: B=4, N=1024, C=768, H=12, d=64
// fp16-split (3-term) mma.sync GEMMs + fp32 softmax/mix.
// Round 13 (= round 11 resubmit; round 12 was an infra failure):
// single-barrier 4-stage cp.async pipeline (BK=32, SW64 tiles) for K1/K2/K5;
// K4 rebuilt at BM=64 with 2 CTAs/SM.
// d_out layout: [ out (4096*768) | attn (4*12*1024*1024) ]
// ---------------------------------------------------------------------------

#define BATCH 4
#define SEQ   1024
#define CDIM  768
#define HEADS 12
#define HDIM  64
#define QKVC  2304
#define TOKS  4096
#define OUT_ELEMS (TOKS * CDIM)

__device__ float  g_logits[(size_t)BATCH * HEADS * SEQ * SEQ]; // 201 MB
__device__ __half g_x_hi[TOKS * CDIM],      g_x_lo[TOKS * CDIM];
__device__ __half g_qkv_hi[TOKS * QKVC],    g_qkv_lo[TOKS * QKVC];
__device__ __half g_wqkvt_hi[QKVC * CDIM],  g_wqkvt_lo[QKVC * CDIM];
__device__ __half g_wprojt_hi[CDIM * CDIM], g_wprojt_lo[CDIM * CDIM];
__device__ __half g_vt_hi[BATCH * HEADS * HDIM * SEQ], g_vt_lo[BATCH * HEADS * HDIM * SEQ];
__device__ __half g_ctx_hi[TOKS * CDIM],    g_ctx_lo[TOKS * CDIM];

// ------------------------------ asm helpers --------------------------------
__device__ __forceinline__ uint32_t smem_to_u32(const void* p) {
    uint32_t a;
    asm("{ .reg .u64 t; cvta.to.shared.u64 t, %1; cvt.u32.u64 %0, t; }" : "=r"(a) : "l"(p));
    return a;
}
#define LDSM4(d0, d1, d2, d3, a) \
    asm volatile("ldmatrix.sync.aligned.m8n8.x4.shared.b16 {%0,%1,%2,%3}, [%4];" \
                 : "=r"(d0), "=r"(d1), "=r"(d2), "=r"(d3) : "r"(a))
#define MMA16816(c, a, b) \
    asm volatile("mma.sync.aligned.m16n8k16.row.col.f32.f16.f16.f32 " \
                 "{%0,%1,%2,%3}, {%4,%5,%6,%7}, {%8,%9}, {%0,%1,%2,%3};" \
                 : "+f"((c)[0]), "+f"((c)[1]), "+f"((c)[2]), "+f"((c)[3]) \
                 : "r"((a)[0]), "r"((a)[1]), "r"((a)[2]), "r"((a)[3]), \
                   "r"((b)[0]), "r"((b)[1]))
#define CP_ASYNC16(sm, gp) \
    asm volatile("cp.async.cg.shared.global [%0], [%1], 16;" :: "r"(sm), "l"(gp))
#define CP_COMMIT() asm volatile("cp.async.commit_group;" ::: "memory")

// split fp32x4 -> fp16 hi/lo, store 8B each to SW128-swizzled smem (K4 A path)
__device__ __forceinline__ void split_store_h(float4 v, char* hi, char* lo, int off) {
    const int sw = off ^ ((off >> 3) & 0x70);
    __half2 h01 = __floats2half2_rn(v.x, v.y);
    __half2 h23 = __floats2half2_rn(v.z, v.w);
    *(uint2*)(hi + sw) = make_uint2(*(uint32_t*)&h01, *(uint32_t*)&h23);
    float2 f01 = __half22float2(h01), f23 = __half22float2(h23);
    __half2 l01 = __floats2half2_rn(v.x - f01.x, v.y - f01.y);
    __half2 l23 = __floats2half2_rn(v.z - f23.x, v.w - f23.y);
    *(uint2*)(lo + sw) = make_uint2(*(uint32_t*)&l01, *(uint32_t*)&l23);
}

// ---------------------------------------------------------------------------
// Pipelined GEMM (MODE 0=K1, 1=K2, 3=K5): D[M,N] = A[M,K].B[N,K]^T.
// BM=128, BN=64, BK=32, 4-stage single-barrier cp.async ring, SW64 tiles.
// All operands pre-split fp16 hi/lo in gmem.
// ---------------------------------------------------------------------------
template <int MODE>
__global__ __launch_bounds__(256, 2)
void tc_gemm(const __half* __restrict__ Ah_gp, const __half* __restrict__ Al_gp,
             const __half* __restrict__ Bh_gp, const __half* __restrict__ Bl_gp,
             const float* __restrict__ bias, void* Ca, void* Cb)
{
    constexpr bool C_SPLIT = (MODE == 0);
    constexpr int BN    = 64;
    constexpr int K_TOT = (MODE == 1) ? 64 : 768;
    constexpr int LDA   = (MODE == 0) ? CDIM : (MODE == 1) ? QKVC : CDIM;
    constexpr int LDB   = (MODE == 1) ? QKVC : CDIM;
    constexpr int LDC   = (MODE == 0) ? QKVC : (MODE == 1) ? SEQ : CDIM;
    constexpr int NITER = K_TOT / 32;
    constexpr int S     = 4;
    constexpr int WAITN = (S - 2 < NITER - 1) ? S - 2 : NITER - 1;
    constexpr int NPRO  = (S - 1 < NITER) ? S - 1 : NITER;
    constexpr int WM    = 2;
    constexpr int OFF_AL = 8192;
    constexpr int OFF_BH = 16384;
    constexpr int OFF_BL = 20480;
    constexpr int STAGE  = 24576;

    extern __shared__ char smem[];
    const uint32_t smem_base = smem_to_u32(smem);
    const int tid  = threadIdx.x;
    const int warp = tid >> 5;
    const int lane = tid & 31;
    const int wmBase = (warp >> 1) * 32;
    const int wnBase = (warp & 1) * 32;

    const int row0 = blockIdx.y * 128;
    const int col0 = blockIdx.x * BN;
    const int z = blockIdx.z;

    size_t aOff = 0, bOff = 0, cOff = 0;
    if (MODE == 1) {
        const int b = z / HEADS, h = z % HEADS;
        aOff = (size_t)b * SEQ * QKVC + (size_t)h * HDIM;
        bOff = aOff + CDIM;
        cOff = (size_t)z * SEQ * SEQ;
    }
    const __half* Ah_g = Ah_gp + aOff;
    const __half* Al_g = Al_gp + aOff;
    const __half* Bh_g = Bh_gp + bOff;
    const __half* Bl_g = Bl_gp + bOff;
    float*  Cf = (float*)Ca + cOff;
    __half* Ch = (__half*)Ca + cOff;
    __half* Cl = (__half*)Cb + cOff;

    float acc[WM][4][4];
#pragma unroll
    for (int i = 0; i < WM; i++)
#pragma unroll
        for (int j = 0; j < 4; j++)
#pragma unroll
            for (int e = 0; e < 4; e++) acc[i][j][e] = 0.0f;

    // stage tiles: 64B rows, SW64 swizzle (off ^ ((off>>3)&0x30))
    auto issue_stage = [&](int s, int k0) {
        const uint32_t sb = smem_base + s * STAGE;
        // A hi/lo: 128 rows x 4 chunks = 512 -> 2 per thread each
#pragma unroll
        for (int l = 0; l < 2; l++) {
            const int c = tid + l * 256;
            const int row = c >> 2, cc = c & 3;
            int off = row * 64 + cc * 16;
            off ^= (off >> 3) & 0x30;
            CP_ASYNC16(sb + off,          Ah_g + (size_t)(row0 + row) * LDA + k0 + cc * 8);
            CP_ASYNC16(sb + OFF_AL + off, Al_g + (size_t)(row0 + row) * LDA + k0 + cc * 8);
        }
        // B hi/lo: 64 rows x 4 chunks = 256 -> 1 per thread each
        {
            const int row = tid >> 2, cc = tid & 3;
            int off = row * 64 + cc * 16;
            off ^= (off >> 3) & 0x30;
            CP_ASYNC16(sb + OFF_BH + off, Bh_g + (size_t)(col0 + row) * LDB + k0 + cc * 8);
            CP_ASYNC16(sb + OFF_BL + off, Bl_g + (size_t)(col0 + row) * LDB + k0 + cc * 8);
        }
    };
    auto compute = [&](int s) {
        const uint32_t sb = smem_base + s * STAGE;
        const int r = lane & 7, g = lane >> 3;
#pragma unroll
        for (int kk = 0; kk < 2; kk++) {
            uint32_t ah[WM][4], al[WM][4];
#pragma unroll
            for (int i = 0; i < WM; i++) {
                const int row = wmBase + i * 16 + (g & 1) * 8 + r;
                int off = row * 64 + kk * 32 + (g >> 1) * 16;
                off ^= (off >> 3) & 0x30;
                LDSM4(ah[i][0], ah[i][1], ah[i][2], ah[i][3], sb + off);
                LDSM4(al[i][0], al[i][1], al[i][2], al[i][3], sb + OFF_AL + off);
            }
            uint32_t bh[4][2], bl[4][2];
#pragma unroll
            for (int jp = 0; jp < 2; jp++) {
                const int n = wnBase + jp * 16 + (g >> 1) * 8 + r;
                int off = n * 64 + kk * 32 + (g & 1) * 16;
                off ^= (off >> 3) & 0x30;
                LDSM4(bh[2 * jp][0], bh[2 * jp][1], bh[2 * jp + 1][0], bh[2 * jp + 1][1],
                      sb + OFF_BH + off);
                LDSM4(bl[2 * jp][0], bl[2 * jp][1], bl[2 * jp + 1][0], bl[2 * jp + 1][1],
                      sb + OFF_BL + off);
            }
#pragma unroll
            for (int i = 0; i < WM; i++)
#pragma unroll
                for (int j = 0; j < 4; j++) {
                    MMA16816(acc[i][j], ah[i], bh[j]);
                    MMA16816(acc[i][j], ah[i], bl[j]);
                    MMA16816(acc[i][j], al[i], bh[j]);
                }
        }
    };

    // prologue: fill S-1 stages (or all NITER if fewer)
#pragma unroll
    for (int s = 0; s < NPRO; s++) {
        issue_stage(s, s * 32);
        CP_COMMIT();
    }

    for (int it = 0; it < NITER; it++) {
        asm volatile("cp.async.wait_group %0;" :: "n"(WAITN) : "memory");
        __syncthreads();
        compute(it % S);
        const int nf = it + S - 1;
        if (nf < NITER) issue_stage(nf % S, nf * 32);
        CP_COMMIT();
    }

    // epilogue
    const int qr = lane >> 2;
    const int qc = (lane & 3) * 2;
#pragma unroll
    for (int i = 0; i < WM; i++) {
#pragma unroll
        for (int j = 0; j < 4; j++) {
            const int gr = row0 + wmBase + i * 16 + qr;
            const int gc = col0 + wnBase + j * 8 + qc;
            float v0 = acc[i][j][0], v1 = acc[i][j][1];
            float v2 = acc[i][j][2], v3 = acc[i][j][3];
            if (MODE == 0 || MODE == 3) {
                const float b0 = bias[gc], b1 = bias[gc + 1];
                v0 += b0; v1 += b1; v2 += b0; v3 += b1;
            }
            if (MODE == 0) {
                if (gc < CDIM)     { v0 *= 0.125f; v2 *= 0.125f; }
                if (gc + 1 < CDIM) { v1 *= 0.125f; v3 *= 0.125f; }
            }
            if (C_SPLIT) {
                __half2 h0 = __floats2half2_rn(v0, v1);
                __half2 h1 = __floats2half2_rn(v2, v3);
                *(__half2*)&Ch[(size_t)gr * LDC + gc]       = h0;
                *(__half2*)&Ch[(size_t)(gr + 8) * LDC + gc] = h1;
                float2 f0 = __half22float2(h0), f1 = __half22float2(h1);
                *(__half2*)&Cl[(size_t)gr * LDC + gc]       = __floats2half2_rn(v0 - f0.x, v1 - f0.y);
                *(__half2*)&Cl[(size_t)(gr + 8) * LDC + gc] = __floats2half2_rn(v2 - f1.x, v3 - f1.y);
            } else {
                *(float2*)&Cf[(size_t)gr * LDC + gc]       = make_float2(v0, v1);
                *(float2*)&Cf[(size_t)(gr + 8) * LDC + gc] = make_float2(v2, v3);
            }
        }
    }
}

// ---------------------------------------------------------------------------
// K4: ctx = attn @ vt^T per (b,h). BM=64, BN=64, BK=64, 2-stage, 2 CTAs/SM.
// A (fp32 attn) runtime-split; B (vt hi/lo) via cp.async. SW128 tiles.
// ---------------------------------------------------------------------------
__global__ __launch_bounds__(256, 2)
void tc_gemm_av(const float* __restrict__ Ag,
                const __half* __restrict__ Bh_gp, const __half* __restrict__ Bl_gp,
                __half* __restrict__ Chp, __half* __restrict__ Clp)
{
    constexpr int NITER = SEQ / 64;   // 16
    constexpr int AREG  = 4;
    constexpr int OFF_AL = 8192;
    constexpr int OFF_BH = 16384;
    constexpr int OFF_BL = 24576;
    constexpr int STAGE  = 32768;

    extern __shared__ char smem[];
    const uint32_t smem_base = smem_to_u32(smem);
    const int tid  = threadIdx.x;
    const int warp = tid >> 5;
    const int lane = tid & 31;
    const int wmBase = (warp >> 1) * 16;
    const int wnBase = (warp & 1) * 32;

    const int row0 = blockIdx.y * 64;
    const int z = blockIdx.z;
    const float*  Af   = Ag + (size_t)z * SEQ * SEQ;
    const __half* Bh_g = Bh_gp + (size_t)z * HDIM * SEQ;
    const __half* Bl_g = Bl_gp + (size_t)z * HDIM * SEQ;
    const size_t cOff = (size_t)(z / HEADS) * SEQ * CDIM + (size_t)(z % HEADS) * HDIM;
    __half* Ch = Chp + cOff;
    __half* Cl = Clp + cOff;

    float acc[4][4];
#pragma unroll
    for (int j = 0; j < 4; j++)
#pragma unroll
        for (int e = 0; e < 4; e++) acc[j][e] = 0.0f;

    float4 aRf[AREG];

    auto issue_B = [&](int p, int k0) {
        const uint32_t sb = smem_base + p * STAGE;
#pragma unroll
        for (int l = 0; l < 2; l++) {
            const int c = tid + l * 256;
            const int row = c >> 3, cc = c & 7;
            int off = row * 128 + cc * 16;
            off ^= (off >> 3) & 0x70;
            CP_ASYNC16(sb + OFF_BH + off, Bh_g + (size_t)row * SEQ + k0 + cc * 8);
            CP_ASYNC16(sb + OFF_BL + off, Bl_g + (size_t)row * SEQ + k0 + cc * 8);
        }
    };
    auto loadA = [&](int k0) {
#pragma unroll
        for (int l = 0; l < AREG; l++) {
            const int g = tid + l * 256;
            aRf[l] = *(const float4*)&Af[(size_t)(row0 + (g >> 4)) * SEQ + k0 + (g & 15) * 4];
        }
    };
    auto storeA = [&](int p) {
        char* base = smem + p * STAGE;
#pragma unroll
        for (int l = 0; l < AREG; l++) {
            const int g = tid + l * 256;
            split_store_h(aRf[l], base, base + OFF_AL, (g >> 4) * 128 + (g & 15) * 8);
        }
    };
    auto compute = [&](int p, int kkBeg, int kkEnd) {
        const uint32_t sb = smem_base + p * STAGE;
        const int r = lane & 7, g = lane >> 3;
        for (int kk = kkBeg; kk < kkEnd; kk++) {
            uint32_t ah[4], al[4];
            {
                const int row = wmBase + (g & 1) * 8 + r;
                int off = row * 128 + kk * 32 + (g >> 1) * 16;
                off ^= (off >> 3) & 0x70;
                LDSM4(ah[0], ah[1], ah[2], ah[3], sb + off);
                LDSM4(al[0], al[1], al[2], al[3], sb + OFF_AL + off);
            }
            uint32_t bh[4][2], bl[4][2];
#pragma unroll
            for (int jp = 0; jp < 2; jp++) {
                const int n = wnBase + jp * 16 + (g >> 1) * 8 + r;
                int off = n * 128 + kk * 32 + (g & 1) * 16;
                off ^= (off >> 3) & 0x70;
                LDSM4(bh[2 * jp][0], bh[2 * jp][1], bh[2 * jp + 1][0], bh[2 * jp + 1][1],
                      sb + OFF_BH + off);
                LDSM4(bl[2 * jp][0], bl[2 * jp][1], bl[2 * jp + 1][0], bl[2 * jp + 1][1],
                      sb + OFF_BL + off);
            }
#pragma unroll
            for (int j = 0; j < 4; j++) {
                MMA16816(acc[j], ah, bh[j]);
                MMA16816(acc[j], ah, bl[j]);
                MMA16816(acc[j], al, bh[j]);
            }
        }
    };

    loadA(0);
    issue_B(0, 0);
    CP_COMMIT();
    storeA(0);

    for (int it = 0; it < NITER; it++) {
        const int p = it & 1;
        const bool more = (it + 1 < NITER);
        if (more) {
            issue_B(p ^ 1, (it + 1) * 64);
            CP_COMMIT();
            loadA((it + 1) * 64);
        }
        if (more) asm volatile("cp.async.wait_group 1;" ::: "memory");
        else      asm volatile("cp.async.wait_group 0;" ::: "memory");
        __syncthreads();
        compute(p, 0, 2);
        if (more) storeA(p ^ 1);
        compute(p, 2, 4);
        __syncthreads();
    }

    const int qr = lane >> 2;
    const int qc = (lane & 3) * 2;
#pragma unroll
    for (int j = 0; j < 4; j++) {
        const int gr = row0 + wmBase + qr;
        const int gc = (warp & 1) * 32 + j * 8 + qc;
        float v0 = acc[j][0], v1 = acc[j][1], v2 = acc[j][2], v3 = acc[j][3];
        __half2 h0 = __floats2half2_rn(v0, v1);
        __half2 h1 = __floats2half2_rn(v2, v3);
        *(__half2*)&Ch[(size_t)gr * CDIM + gc]       = h0;
        *(__half2*)&Ch[(size_t)(gr + 8) * CDIM + gc] = h1;
        float2 f0 = __half22float2(h0), f1 = __half22float2(h1);
        *(__half2*)&Cl[(size_t)gr * CDIM + gc]       = __floats2half2_rn(v0 - f0.x, v1 - f0.y);
        *(__half2*)&Cl[(size_t)(gr + 8) * CDIM + gc] = __floats2half2_rn(v2 - f1.x, v3 - f1.y);
    }
}

// ---------------------------------------------------------------------------
// P0: presplit fp32 -> fp16 hi/lo
// ---------------------------------------------------------------------------
__global__ void presplit(const float* __restrict__ in,
                         __half* __restrict__ hi, __half* __restrict__ lo, int n4)
{
    const int i = blockIdx.x * blockDim.x + threadIdx.x;
    if (i >= n4) return;
    float4 v = ((const float4*)in)[i];
    __half2 h01 = __floats2half2_rn(v.x, v.y);
    __half2 h23 = __floats2half2_rn(v.z, v.w);
    ((__half2*)hi)[2 * i]     = h01;
    ((__half2*)hi)[2 * i + 1] = h23;
    float2 f01 = __half22float2(h01), f23 = __half22float2(h23);
    ((__half2*)lo)[2 * i]     = __floats2half2_rn(v.x - f01.x, v.y - f01.y);
    ((__half2*)lo)[2 * i + 1] = __floats2half2_rn(v.z - f23.x, v.w - f23.y);
}

// ---------------------------------------------------------------------------
// P1/P2: transpose fp32 [rows][cols] -> fp16 hi/lo [cols][rows]
// ---------------------------------------------------------------------------
__global__ void transpose_split(const float* __restrict__ in,
                                __half* __restrict__ hi, __half* __restrict__ lo,
                                int rows, int cols)
{
    __shared__ float t[32][33];
    const int x = blockIdx.x * 32 + threadIdx.x;
    const int y0 = blockIdx.y * 32;
#pragma unroll
    for (int j = threadIdx.y; j < 32; j += 8)
        t[j][threadIdx.x] = in[(size_t)(y0 + j) * cols + x];
    __syncthreads();
    const int x2 = y0 + threadIdx.x;
    const int y2 = blockIdx.x * 32;
#pragma unroll
    for (int j = threadIdx.y; j < 32; j += 8) {
        const float v = t[threadIdx.x][j];
        const __half h = __float2half_rn(v);
        hi[(size_t)(y2 + j) * rows + x2] = h;
        lo[(size_t)(y2 + j) * rows + x2] = __float2half_rn(v - __half2float(h));
    }
}

// ---------------------------------------------------------------------------
// P3: transpose v slice of qkv_hi/lo -> vt_hi/lo [bh][d][m]
// ---------------------------------------------------------------------------
__global__ void vt_split(const __half* __restrict__ qh, const __half* __restrict__ ql,
                         __half* __restrict__ vh, __half* __restrict__ vl)
{
    __shared__ __half th[32][33], tl[32][33];
    const int z = blockIdx.z;
    const int b = z / HEADS, h = z % HEADS;
    const size_t inBase = (size_t)b * SEQ * QKVC + 2 * CDIM + (size_t)h * HDIM;
    const int m0 = blockIdx.x * 32, d0 = blockIdx.y * 32;
#pragma unroll
    for (int j = threadIdx.y; j < 32; j += 8) {
        const size_t idx = inBase + (size_t)(m0 + j) * QKVC + d0 + threadIdx.x;
        th[j][threadIdx.x] = qh[idx];
        tl[j][threadIdx.x] = ql[idx];
    }
    __syncthreads();
    const size_t outBase = (size_t)z * HDIM * SEQ;
#pragma unroll
    for (int j = threadIdx.y; j < 32; j += 8) {
        const size_t idx = outBase + (size_t)(d0 + j) * SEQ + m0 + threadIdx.x;
        vh[idx] = th[threadIdx.x][j];
        vl[idx] = tl[threadIdx.x][j];
    }
}

// ---------------------------------------------------------------------------
// K3 (fp32, register-resident): per (b,n): mix1 -> softmax -> mix2 -> attn
// ---------------------------------------------------------------------------
__global__ __launch_bounds__(256)
void mix_softmax_kernel(const float* __restrict__ logits,
                        const float* __restrict__ W_l, const float* __restrict__ b_l,
                        const float* __restrict__ W_w, const float* __restrict__ b_w,
                        float* __restrict__ attn_out)
{
    __shared__ float swl[HEADS * HEADS], sww[HEADS * HEADS];
    __shared__ float sbl[HEADS], sbw[HEADS];
    __shared__ float red[HEADS][8];

    const int tid  = threadIdx.x;
    const int lane = tid & 31;
    const int warp = tid >> 5;
    const int bn = blockIdx.x;
    const int b = bn >> 10;
    const int n = bn & (SEQ - 1);

    if (tid < HEADS * HEADS) { swl[tid] = W_l[tid]; sww[tid] = W_w[tid]; }
    if (tid < HEADS) { sbl[tid] = b_l[tid]; sbw[tid] = b_w[tid]; }
    __syncthreads();

    const float* lb = logits + ((size_t)b * HEADS * SEQ + n) * SEQ + tid * 4;
    float4 l[HEADS];
#pragma unroll
    for (int h = 0; h < HEADS; h++)
        l[h] = *(const float4*)&lb[(size_t)h * SEQ * SEQ];

    float4 m1[HEADS];
#pragma unroll
    for (int k = 0; k < HEADS; k++) {
        float bk = sbl[k];
        float4 a = make_float4(bk, bk, bk, bk);
#pragma unroll
        for (int h = 0; h < HEADS; h++) {
            const float w = swl[h * HEADS + k];
            a.x = fmaf(l[h].x, w, a.x);
            a.y = fmaf(l[h].y, w, a.y);
            a.z = fmaf(l[h].z, w, a.z);
            a.w = fmaf(l[h].w, w, a.w);
        }
        m1[k] = a;
    }

    float rowmax[HEADS];
#pragma unroll
    for (int k = 0; k < HEADS; k++) {
        float v = fmaxf(fmaxf(m1[k].x, m1[k].y), fmaxf(m1[k].z, m1[k].w));
#pragma unroll
        for (int o = 16; o > 0; o >>= 1) v = fmaxf(v, __shfl_xor_sync(0xffffffff, v, o));
        if (lane == 0) red[k][warp] = v;
    }
    __syncthreads();
#pragma unroll
    for (int k = 0; k < HEADS; k++) {
        float v = red[k][0];
#pragma unroll
        for (int w = 1; w < 8; w++) v = fmaxf(v, red[k][w]);
        rowmax[k] = v;
    }
    __syncthreads();

    float inv[HEADS];
#pragma unroll
    for (int k = 0; k < HEADS; k++) {
        m1[k].x = __expf(m1[k].x - rowmax[k]);
        m1[k].y = __expf(m1[k].y - rowmax[k]);
        m1[k].z = __expf(m1[k].z - rowmax[k]);
        m1[k].w = __expf(m1[k].w - rowmax[k]);
        float s = (m1[k].x + m1[k].y) + (m1[k].z + m1[k].w);
#pragma unroll
        for (int o = 16; o > 0; o >>= 1) s += __shfl_xor_sync(0xffffffff, s, o);
        if (lane == 0) red[k][warp] = s;
    }
    __syncthreads();
#pragma unroll
    for (int k = 0; k < HEADS; k++) {
        float s = red[k][0];
#pragma unroll
        for (int w = 1; w < 8; w++) s += red[k][w];
        inv[k] = 1.0f / s;
    }

#pragma unroll
    for (int h = 0; h < HEADS; h++) {
        m1[h].x *= inv[h]; m1[h].y *= inv[h];
        m1[h].z *= inv[h]; m1[h].w *= inv[h];
    }

    float* ob = attn_out + ((size_t)b * HEADS * SEQ + n) * SEQ + tid * 4;
#pragma unroll
    for (int k = 0; k < HEADS; k++) {
        float bk = sbw[k];
        float4 a = make_float4(bk, bk, bk, bk);
#pragma unroll
        for (int h = 0; h < HEADS; h++) {
            const float w = sww[h * HEADS + k];
            a.x = fmaf(m1[h].x, w, a.x);
            a.y = fmaf(m1[h].y, w, a.y);
            a.z = fmaf(m1[h].z, w, a.z);
            a.w = fmaf(m1[h].w, w, a.w);
        }
        *(float4*)&ob[(size_t)k * SEQ * SEQ] = a;
    }
}

// ---------------------------------------------------------------------------
extern "C" void kernel_launch(void* const* d_in, const int* in_sizes, int n_in,
                              void* d_out, int out_size)
{
    const float* x      = (const float*)d_in[0];
    const float* W_qkv  = (const float*)d_in[1];
    const float* b_qkv  = (const float*)d_in[2];
    const float* W_l    = (const float*)d_in[3];
    const float* b_l    = (const float*)d_in[4];
    const float* W_w    = (const float*)d_in[5];
    const float* b_w    = (const float*)d_in[6];
    const float* W_proj = (const float*)d_in[7];
    const float* b_proj = (const float*)d_in[8];

    float* out  = (float*)d_out;
    float* attn = out + OUT_ELEMS;

    float* logits_p;
    __half *xh, *xl, *qh, *ql, *wqh, *wql, *wph, *wpl, *vh, *vl, *ch, *cl;
    cudaGetSymbolAddress((void**)&logits_p, g_logits);
    cudaGetSymbolAddress((void**)&xh, g_x_hi);      cudaGetSymbolAddress((void**)&xl, g_x_lo);
    cudaGetSymbolAddress((void**)&qh, g_qkv_hi);    cudaGetSymbolAddress((void**)&ql, g_qkv_lo);
    cudaGetSymbolAddress((void**)&wqh, g_wqkvt_hi); cudaGetSymbolAddress((void**)&wql, g_wqkvt_lo);
    cudaGetSymbolAddress((void**)&wph, g_wprojt_hi);cudaGetSymbolAddress((void**)&wpl, g_wprojt_lo);
    cudaGetSymbolAddress((void**)&vh, g_vt_hi);     cudaGetSymbolAddress((void**)&vl, g_vt_lo);
    cudaGetSymbolAddress((void**)&ch, g_ctx_hi);    cudaGetSymbolAddress((void**)&cl, g_ctx_lo);

    const int smemPipe = 4 * 24576;   // 98304 (modes 0/3)
    const int smemK2   = 2 * 24576;   // 49152 (NITER=2 uses stages 0/1 only)
    const int smemK4   = 2 * 32768;   // 65536
    cudaFuncSetAttribute(tc_gemm<0>, cudaFuncAttributeMaxDynamicSharedMemorySize, smemPipe);
    cudaFuncSetAttribute(tc_gemm<1>, cudaFuncAttributeMaxDynamicSharedMemorySize, smemK2);
    cudaFuncSetAttribute(tc_gemm<3>, cudaFuncAttributeMaxDynamicSharedMemorySize, smemPipe);
    cudaFuncSetAttribute(tc_gemm_av, cudaFuncAttributeMaxDynamicSharedMemorySize, smemK4);

    // P0: presplit x
    presplit<<<(TOKS * CDIM / 4 + 255) / 256, 256>>>(x, xh, xl, TOKS * CDIM / 4);

    // P1/P2: transpose+split weights -> [N][K] fp16 hi/lo
    transpose_split<<<dim3(QKVC / 32, CDIM / 32), dim3(32, 8)>>>(W_qkv, wqh, wql, CDIM, QKVC);
    transpose_split<<<dim3(CDIM / 32, CDIM / 32), dim3(32, 8)>>>(W_proj, wph, wpl, CDIM, CDIM);

    // K1: qkv = x @ W_qkv^T' + b (q scaled) -> qkv_hi/lo
    tc_gemm<0><<<dim3(QKVC / 64, TOKS / 128, 1), 256, smemPipe>>>(
        xh, xl, wqh, wql, b_qkv, qh, ql);

    // P3: v transpose -> vt_hi/lo [bh][d][m]
    vt_split<<<dim3(SEQ / 32, HDIM / 32, BATCH * HEADS), dim3(32, 8)>>>(qh, ql, vh, vl);

    // K2: logits = q @ k^T per (b,h)  (fp32 out)
    tc_gemm<1><<<dim3(SEQ / 64, SEQ / 128, BATCH * HEADS), 256, smemK2>>>(
        qh, ql, qh, ql, nullptr, logits_p, nullptr);

    // K3: mix -> softmax -> mix -> attn output (fp32)
    mix_softmax_kernel<<<TOKS, 256>>>(logits_p, W_l, b_l, W_w, b_w, attn);

    // K4: ctx = attn @ vt^T per (b,h) -> ctx_hi/lo
    tc_gemm_av<<<dim3(1, SEQ / 64, BATCH * HEADS), 256, smemK4>>>(
        attn, vh, vl, ch, cl);

    // K5: out = ctx @ W_proj^T' + b (fp32 out)
    tc_gemm<3><<<dim3(CDIM / 64, TOKS / 128, 1), 256, smemPipe>>>(
        ch, cl, wph, wpl, b_proj, out, nullptr);
}

// round 14
// speedup vs baseline: 1.0451x; 1.0445x over previous
#include <cuda_runtime.h>
#include <cuda_fp16.h>
#include <cstdint>

// ---------------------------------------------------------------------------
// TalkingHeadAttention: B=4, N=1024, C=768, H=12, d=64
// fp16-split (3-term) mma.sync GEMMs + fp32 softmax/mix.
// Round 14: best-known recombination — K1/K2/K5 = round-10 config (BK=64,
// 2-stage, BN=64, occ 2); K4 = round-13 rebuild (BM=64, occ 2, grid 768).
// d_out layout: [ out (4096*768) | attn (4*12*1024*1024) ]
// ---------------------------------------------------------------------------

#define BATCH 4
#define SEQ   1024
#define CDIM  768
#define HEADS 12
#define HDIM  64
#define QKVC  2304
#define TOKS  4096
#define OUT_ELEMS (TOKS * CDIM)

__device__ float  g_logits[(size_t)BATCH * HEADS * SEQ * SEQ]; // 201 MB
__device__ __half g_x_hi[TOKS * CDIM],      g_x_lo[TOKS * CDIM];
__device__ __half g_qkv_hi[TOKS * QKVC],    g_qkv_lo[TOKS * QKVC];
__device__ __half g_wqkvt_hi[QKVC * CDIM],  g_wqkvt_lo[QKVC * CDIM];
__device__ __half g_wprojt_hi[CDIM * CDIM], g_wprojt_lo[CDIM * CDIM];
__device__ __half g_vt_hi[BATCH * HEADS * HDIM * SEQ], g_vt_lo[BATCH * HEADS * HDIM * SEQ];
__device__ __half g_ctx_hi[TOKS * CDIM],    g_ctx_lo[TOKS * CDIM];

// ------------------------------ asm helpers --------------------------------
__device__ __forceinline__ uint32_t smem_to_u32(const void* p) {
    uint32_t a;
    asm("{ .reg .u64 t; cvta.to.shared.u64 t, %1; cvt.u32.u64 %0, t; }" : "=r"(a) : "l"(p));
    return a;
}
#define LDSM4(d0, d1, d2, d3, a) \
    asm volatile("ldmatrix.sync.aligned.m8n8.x4.shared.b16 {%0,%1,%2,%3}, [%4];" \
                 : "=r"(d0), "=r"(d1), "=r"(d2), "=r"(d3) : "r"(a))
#define MMA16816(c, a, b) \
    asm volatile("mma.sync.aligned.m16n8k16.row.col.f32.f16.f16.f32 " \
                 "{%0,%1,%2,%3}, {%4,%5,%6,%7}, {%8,%9}, {%0,%1,%2,%3};" \
                 : "+f"((c)[0]), "+f"((c)[1]), "+f"((c)[2]), "+f"((c)[3]) \
                 : "r"((a)[0]), "r"((a)[1]), "r"((a)[2]), "r"((a)[3]), \
                   "r"((b)[0]), "r"((b)[1]))
#define CP_ASYNC16(sm, gp) \
    asm volatile("cp.async.cg.shared.global [%0], [%1], 16;" :: "r"(sm), "l"(gp))
#define CP_COMMIT() asm volatile("cp.async.commit_group;" ::: "memory")
#define CP_WAIT0()  asm volatile("cp.async.wait_group 0;" ::: "memory")
#define CP_WAIT1()  asm volatile("cp.async.wait_group 1;" ::: "memory")

// split fp32x4 -> fp16 hi/lo, store 8B each to SW128-swizzled smem (K4 A path)
__device__ __forceinline__ void split_store_h(float4 v, char* hi, char* lo, int off) {
    const int sw = off ^ ((off >> 3) & 0x70);
    __half2 h01 = __floats2half2_rn(v.x, v.y);
    __half2 h23 = __floats2half2_rn(v.z, v.w);
    *(uint2*)(hi + sw) = make_uint2(*(uint32_t*)&h01, *(uint32_t*)&h23);
    float2 f01 = __half22float2(h01), f23 = __half22float2(h23);
    __half2 l01 = __floats2half2_rn(v.x - f01.x, v.y - f01.y);
    __half2 l23 = __floats2half2_rn(v.z - f23.x, v.w - f23.y);
    *(uint2*)(lo + sw) = make_uint2(*(uint32_t*)&l01, *(uint32_t*)&l23);
}

// ---------------------------------------------------------------------------
// GEMM (MODE 0=K1 bias+qscale+split-out, 1=K2 fp32-out, 3=K5 bias+fp32-out):
// D[M,N] = A[M,K] . B[N,K]^T.  BM=128, BN=64, BK=64, 2-stage cp.async,
// SW128 tiles, 2 CTAs/SM. Warps 4x2, warp tile 32x32. (round-10 proven)
// ---------------------------------------------------------------------------
template <int MODE>
__global__ __launch_bounds__(256, 2)
void tc_gemm(const __half* __restrict__ Ah_gp, const __half* __restrict__ Al_gp,
             const __half* __restrict__ Bh_gp, const __half* __restrict__ Bl_gp,
             const float* __restrict__ bias, void* Ca, void* Cb)
{
    constexpr bool C_SPLIT = (MODE == 0);
    constexpr int BN    = 64;
    constexpr int K_TOT = (MODE == 1) ? 64 : 768;
    constexpr int LDA   = (MODE == 0) ? CDIM : (MODE == 1) ? QKVC : CDIM;
    constexpr int LDB   = (MODE == 1) ? QKVC : CDIM;
    constexpr int LDC   = (MODE == 0) ? QKVC : (MODE == 1) ? SEQ : CDIM;
    constexpr int NITER = K_TOT / 64;
    constexpr int WM    = 2;
    constexpr int OFF_AL = 16384;
    constexpr int OFF_BH = 32768;
    constexpr int OFF_BL = 32768 + BN * 128;
    constexpr int STAGE  = 32768 + 2 * BN * 128;   // 49152

    extern __shared__ char smem[];
    const uint32_t smem_base = smem_to_u32(smem);
    const int tid  = threadIdx.x;
    const int warp = tid >> 5;
    const int lane = tid & 31;
    const int wmBase = (warp >> 1) * 32;
    const int wnBase = (warp & 1) * 32;

    const int row0 = blockIdx.y * 128;
    const int col0 = blockIdx.x * BN;
    const int z = blockIdx.z;

    size_t aOff = 0, bOff = 0, cOff = 0;
    if (MODE == 1) {
        const int b = z / HEADS, h = z % HEADS;
        aOff = (size_t)b * SEQ * QKVC + (size_t)h * HDIM;
        bOff = aOff + CDIM;
        cOff = (size_t)z * SEQ * SEQ;
    }
    const __half* Ah_g = Ah_gp + aOff;
    const __half* Al_g = Al_gp + aOff;
    const __half* Bh_g = Bh_gp + bOff;
    const __half* Bl_g = Bl_gp + bOff;
    float*  Cf = (float*)Ca + cOff;
    __half* Ch = (__half*)Ca + cOff;
    __half* Cl = (__half*)Cb + cOff;

    float acc[WM][4][4];
#pragma unroll
    for (int i = 0; i < WM; i++)
#pragma unroll
        for (int j = 0; j < 4; j++)
#pragma unroll
            for (int e = 0; e < 4; e++) acc[i][j][e] = 0.0f;

    // cp.async one tile (nrows x 64 halves = nrows x 128B), 16B chunks
    auto issue_tile = [&](uint32_t sbase, const __half* g, int ld, int rb, int k0, int nrows) {
#pragma unroll
        for (int l = 0; l < 4; l++) {
            if (l >= nrows / 32) break;
            const int c = tid + l * 256;
            const int row = c >> 3, cc = c & 7;
            int off = row * 128 + cc * 16;
            off ^= (off >> 3) & 0x70;
            CP_ASYNC16(sbase + off, g + (size_t)(rb + row) * ld + k0 + cc * 8);
        }
    };
    auto issue_stage = [&](int p, int k0) {
        const uint32_t sb = smem_base + p * STAGE;
        issue_tile(sb,          Ah_g, LDA, row0, k0, 128);
        issue_tile(sb + OFF_AL, Al_g, LDA, row0, k0, 128);
        issue_tile(sb + OFF_BH, Bh_g, LDB, col0, k0, BN);
        issue_tile(sb + OFF_BL, Bl_g, LDB, col0, k0, BN);
    };
    auto compute = [&](int p, int kkBeg, int kkEnd) {
        const uint32_t sb = smem_base + p * STAGE;
        const int r = lane & 7, g = lane >> 3;
        for (int kk = kkBeg; kk < kkEnd; kk++) {
            uint32_t ah[WM][4], al[WM][4];
#pragma unroll
            for (int i = 0; i < WM; i++) {
                const int row = wmBase + i * 16 + (g & 1) * 8 + r;
                int off = row * 128 + kk * 32 + (g >> 1) * 16;
                off ^= (off >> 3) & 0x70;
                LDSM4(ah[i][0], ah[i][1], ah[i][2], ah[i][3], sb + off);
                LDSM4(al[i][0], al[i][1], al[i][2], al[i][3], sb + OFF_AL + off);
            }
            uint32_t bh[4][2], bl[4][2];
#pragma unroll
            for (int jp = 0; jp < 2; jp++) {
                const int n = wnBase + jp * 16 + (g >> 1) * 8 + r;
                int off = n * 128 + kk * 32 + (g & 1) * 16;
                off ^= (off >> 3) & 0x70;
                LDSM4(bh[2 * jp][0], bh[2 * jp][1], bh[2 * jp + 1][0], bh[2 * jp + 1][1],
                      sb + OFF_BH + off);
                LDSM4(bl[2 * jp][0], bl[2 * jp][1], bl[2 * jp + 1][0], bl[2 * jp + 1][1],
                      sb + OFF_BL + off);
            }
#pragma unroll
            for (int i = 0; i < WM; i++)
#pragma unroll
                for (int j = 0; j < 4; j++) {
                    MMA16816(acc[i][j], ah[i], bh[j]);
                    MMA16816(acc[i][j], ah[i], bl[j]);
                    MMA16816(acc[i][j], al[i], bh[j]);
                }
        }
    };

    // prologue
    issue_stage(0, 0);
    CP_COMMIT();

    for (int it = 0; it < NITER; it++) {
        const int p = it & 1;
        const bool more = (it + 1 < NITER);
        if (more) {
            issue_stage(p ^ 1, (it + 1) * 64);
            CP_COMMIT();
        }
        if (more) CP_WAIT1(); else CP_WAIT0();
        __syncthreads();
        compute(p, 0, 2);
        compute(p, 2, 4);
        __syncthreads();
    }

    // epilogue: acc (+bias, +qscale) -> fp32 C, or split fp16 hi/lo C
    const int qr = lane >> 2;
    const int qc = (lane & 3) * 2;
#pragma unroll
    for (int i = 0; i < WM; i++) {
#pragma unroll
        for (int j = 0; j < 4; j++) {
            const int gr = row0 + wmBase + i * 16 + qr;
            const int gc = col0 + wnBase + j * 8 + qc;
            float v0 = acc[i][j][0], v1 = acc[i][j][1];
            float v2 = acc[i][j][2], v3 = acc[i][j][3];
            if (MODE == 0 || MODE == 3) {
                const float b0 = bias[gc], b1 = bias[gc + 1];
                v0 += b0; v1 += b1; v2 += b0; v3 += b1;
            }
            if (MODE == 0) {
                if (gc < CDIM)     { v0 *= 0.125f; v2 *= 0.125f; }
                if (gc + 1 < CDIM) { v1 *= 0.125f; v3 *= 0.125f; }
            }
            if (C_SPLIT) {
                __half2 h0 = __floats2half2_rn(v0, v1);
                __half2 h1 = __floats2half2_rn(v2, v3);
                *(__half2*)&Ch[(size_t)gr * LDC + gc]       = h0;
                *(__half2*)&Ch[(size_t)(gr + 8) * LDC + gc] = h1;
                float2 f0 = __half22float2(h0), f1 = __half22float2(h1);
                *(__half2*)&Cl[(size_t)gr * LDC + gc]       = __floats2half2_rn(v0 - f0.x, v1 - f0.y);
                *(__half2*)&Cl[(size_t)(gr + 8) * LDC + gc] = __floats2half2_rn(v2 - f1.x, v3 - f1.y);
            } else {
                *(float2*)&Cf[(size_t)gr * LDC + gc]       = make_float2(v0, v1);
                *(float2*)&Cf[(size_t)(gr + 8) * LDC + gc] = make_float2(v2, v3);
            }
        }
    }
}

// ---------------------------------------------------------------------------
// K4: ctx = attn @ vt^T per (b,h). BM=64, BN=64, BK=64, 2-stage, 2 CTAs/SM.
// A (fp32 attn) runtime-split; B (vt hi/lo) via cp.async. SW128 tiles.
// (round-13 validated)
// ---------------------------------------------------------------------------
__global__ __launch_bounds__(256, 2)
void tc_gemm_av(const float* __restrict__ Ag,
                const __half* __restrict__ Bh_gp, const __half* __restrict__ Bl_gp,
                __half* __restrict__ Chp, __half* __restrict__ Clp)
{
    constexpr int NITER = SEQ / 64;   // 16
    constexpr int AREG  = 4;
    constexpr int OFF_AL = 8192;
    constexpr int OFF_BH = 16384;
    constexpr int OFF_BL = 24576;
    constexpr int STAGE  = 32768;

    extern __shared__ char smem[];
    const uint32_t smem_base = smem_to_u32(smem);
    const int tid  = threadIdx.x;
    const int warp = tid >> 5;
    const int lane = tid & 31;
    const int wmBase = (warp >> 1) * 16;
    const int wnBase = (warp & 1) * 32;

    const int row0 = blockIdx.y * 64;
    const int z = blockIdx.z;
    const float*  Af   = Ag + (size_t)z * SEQ * SEQ;
    const __half* Bh_g = Bh_gp + (size_t)z * HDIM * SEQ;
    const __half* Bl_g = Bl_gp + (size_t)z * HDIM * SEQ;
    const size_t cOff = (size_t)(z / HEADS) * SEQ * CDIM + (size_t)(z % HEADS) * HDIM;
    __half* Ch = Chp + cOff;
    __half* Cl = Clp + cOff;

    float acc[4][4];
#pragma unroll
    for (int j = 0; j < 4; j++)
#pragma unroll
        for (int e = 0; e < 4; e++) acc[j][e] = 0.0f;

    float4 aRf[AREG];

    auto issue_B = [&](int p, int k0) {
        const uint32_t sb = smem_base + p * STAGE;
#pragma unroll
        for (int l = 0; l < 2; l++) {
            const int c = tid + l * 256;
            const int row = c >> 3, cc = c & 7;
            int off = row * 128 + cc * 16;
            off ^= (off >> 3) & 0x70;
            CP_ASYNC16(sb + OFF_BH + off, Bh_g + (size_t)row * SEQ + k0 + cc * 8);
            CP_ASYNC16(sb + OFF_BL + off, Bl_g + (size_t)row * SEQ + k0 + cc * 8);
        }
    };
    auto loadA = [&](int k0) {
#pragma unroll
        for (int l = 0; l < AREG; l++) {
            const int g = tid + l * 256;
            aRf[l] = *(const float4*)&Af[(size_t)(row0 + (g >> 4)) * SEQ + k0 + (g & 15) * 4];
        }
    };
    auto storeA = [&](int p) {
        char* base = smem + p * STAGE;
#pragma unroll
        for (int l = 0; l < AREG; l++) {
            const int g = tid + l * 256;
            split_store_h(aRf[l], base, base + OFF_AL, (g >> 4) * 128 + (g & 15) * 8);
        }
    };
    auto compute = [&](int p, int kkBeg, int kkEnd) {
        const uint32_t sb = smem_base + p * STAGE;
        const int r = lane & 7, g = lane >> 3;
        for (int kk = kkBeg; kk < kkEnd; kk++) {
            uint32_t ah[4], al[4];
            {
                const int row = wmBase + (g & 1) * 8 + r;
                int off = row * 128 + kk * 32 + (g >> 1) * 16;
                off ^= (off >> 3) & 0x70;
                LDSM4(ah[0], ah[1], ah[2], ah[3], sb + off);
                LDSM4(al[0], al[1], al[2], al[3], sb + OFF_AL + off);
            }
            uint32_t bh[4][2], bl[4][2];
#pragma unroll
            for (int jp = 0; jp < 2; jp++) {
                const int n = wnBase + jp * 16 + (g >> 1) * 8 + r;
                int off = n * 128 + kk * 32 + (g & 1) * 16;
                off ^= (off >> 3) & 0x70;
                LDSM4(bh[2 * jp][0], bh[2 * jp][1], bh[2 * jp + 1][0], bh[2 * jp + 1][1],
                      sb + OFF_BH + off);
                LDSM4(bl[2 * jp][0], bl[2 * jp][1], bl[2 * jp + 1][0], bl[2 * jp + 1][1],
                      sb + OFF_BL + off);
            }
#pragma unroll
            for (int j = 0; j < 4; j++) {
                MMA16816(acc[j], ah, bh[j]);
                MMA16816(acc[j], ah, bl[j]);
                MMA16816(acc[j], al, bh[j]);
            }
        }
    };

    loadA(0);
    issue_B(0, 0);
    CP_COMMIT();
    storeA(0);

    for (int it = 0; it < NITER; it++) {
        const int p = it & 1;
        const bool more = (it + 1 < NITER);
        if (more) {
            issue_B(p ^ 1, (it + 1) * 64);
            CP_COMMIT();
            loadA((it + 1) * 64);
        }
        if (more) CP_WAIT1(); else CP_WAIT0();
        __syncthreads();
        compute(p, 0, 2);
        if (more) storeA(p ^ 1);
        compute(p, 2, 4);
        __syncthreads();
    }

    const int qr = lane >> 2;
    const int qc = (lane & 3) * 2;
#pragma unroll
    for (int j = 0; j < 4; j++) {
        const int gr = row0 + wmBase + qr;
        const int gc = (warp & 1) * 32 + j * 8 + qc;
        float v0 = acc[j][0], v1 = acc[j][1], v2 = acc[j][2], v3 = acc[j][3];
        __half2 h0 = __floats2half2_rn(v0, v1);
        __half2 h1 = __floats2half2_rn(v2, v3);
        *(__half2*)&Ch[(size_t)gr * CDIM + gc]       = h0;
        *(__half2*)&Ch[(size_t)(gr + 8) * CDIM + gc] = h1;
        float2 f0 = __half22float2(h0), f1 = __half22float2(h1);
        *(__half2*)&Cl[(size_t)gr * CDIM + gc]       = __floats2half2_rn(v0 - f0.x, v1 - f0.y);
        *(__half2*)&Cl[(size_t)(gr + 8) * CDIM + gc] = __floats2half2_rn(v2 - f1.x, v3 - f1.y);
    }
}

// ---------------------------------------------------------------------------
// P0: presplit fp32 -> fp16 hi/lo
// ---------------------------------------------------------------------------
__global__ void presplit(const float* __restrict__ in,
                         __half* __restrict__ hi, __half* __restrict__ lo, int n4)
{
    const int i = blockIdx.x * blockDim.x + threadIdx.x;
    if (i >= n4) return;
    float4 v = ((const float4*)in)[i];
    __half2 h01 = __floats2half2_rn(v.x, v.y);
    __half2 h23 = __floats2half2_rn(v.z, v.w);
    ((__half2*)hi)[2 * i]     = h01;
    ((__half2*)hi)[2 * i + 1] = h23;
    float2 f01 = __half22float2(h01), f23 = __half22float2(h23);
    ((__half2*)lo)[2 * i]     = __floats2half2_rn(v.x - f01.x, v.y - f01.y);
    ((__half2*)lo)[2 * i + 1] = __floats2half2_rn(v.z - f23.x, v.w - f23.y);
}

// ---------------------------------------------------------------------------
// P1/P2: transpose fp32 [rows][cols] -> fp16 hi/lo [cols][rows]
// ---------------------------------------------------------------------------
__global__ void transpose_split(const float* __restrict__ in,
                                __half* __restrict__ hi, __half* __restrict__ lo,
                                int rows, int cols)
{
    __shared__ float t[32][33];
    const int x = blockIdx.x * 32 + threadIdx.x;
    const int y0 = blockIdx.y * 32;
#pragma unroll
    for (int j = threadIdx.y; j < 32; j += 8)
        t[j][threadIdx.x] = in[(size_t)(y0 + j) * cols + x];
    __syncthreads();
    const int x2 = y0 + threadIdx.x;
    const int y2 = blockIdx.x * 32;
#pragma unroll
    for (int j = threadIdx.y; j < 32; j += 8) {
        const float v = t[threadIdx.x][j];
        const __half h = __float2half_rn(v);
        hi[(size_t)(y2 + j) * rows + x2] = h;
        lo[(size_t)(y2 + j) * rows + x2] = __float2half_rn(v - __half2float(h));
    }
}

// ---------------------------------------------------------------------------
// P3: transpose v slice of qkv_hi/lo -> vt_hi/lo [bh][d][m]
// ---------------------------------------------------------------------------
__global__ void vt_split(const __half* __restrict__ qh, const __half* __restrict__ ql,
                         __half* __restrict__ vh, __half* __restrict__ vl)
{
    __shared__ __half th[32][33], tl[32][33];
    const int z = blockIdx.z;
    const int b = z / HEADS, h = z % HEADS;
    const size_t inBase = (size_t)b * SEQ * QKVC + 2 * CDIM + (size_t)h * HDIM;
    const int m0 = blockIdx.x * 32, d0 = blockIdx.y * 32;
#pragma unroll
    for (int j = threadIdx.y; j < 32; j += 8) {
        const size_t idx = inBase + (size_t)(m0 + j) * QKVC + d0 + threadIdx.x;
        th[j][threadIdx.x] = qh[idx];
        tl[j][threadIdx.x] = ql[idx];
    }
    __syncthreads();
    const size_t outBase = (size_t)z * HDIM * SEQ;
#pragma unroll
    for (int j = threadIdx.y; j < 32; j += 8) {
        const size_t idx = outBase + (size_t)(d0 + j) * SEQ + m0 + threadIdx.x;
        vh[idx] = th[threadIdx.x][j];
        vl[idx] = tl[threadIdx.x][j];
    }
}

// ---------------------------------------------------------------------------
// K3 (fp32, register-resident): per (b,n): mix1 -> softmax -> mix2 -> attn
// ---------------------------------------------------------------------------
__global__ __launch_bounds__(256)
void mix_softmax_kernel(const float* __restrict__ logits,
                        const float* __restrict__ W_l, const float* __restrict__ b_l,
                        const float* __restrict__ W_w, const float* __restrict__ b_w,
                        float* __restrict__ attn_out)
{
    __shared__ float swl[HEADS * HEADS], sww[HEADS * HEADS];
    __shared__ float sbl[HEADS], sbw[HEADS];
    __shared__ float red[HEADS][8];

    const int tid  = threadIdx.x;
    const int lane = tid & 31;
    const int warp = tid >> 5;
    const int bn = blockIdx.x;
    const int b = bn >> 10;
    const int n = bn & (SEQ - 1);

    if (tid < HEADS * HEADS) { swl[tid] = W_l[tid]; sww[tid] = W_w[tid]; }
    if (tid < HEADS) { sbl[tid] = b_l[tid]; sbw[tid] = b_w[tid]; }
    __syncthreads();

    const float* lb = logits + ((size_t)b * HEADS * SEQ + n) * SEQ + tid * 4;
    float4 l[HEADS];
#pragma unroll
    for (int h = 0; h < HEADS; h++)
        l[h] = *(const float4*)&lb[(size_t)h * SEQ * SEQ];

    float4 m1[HEADS];
#pragma unroll
    for (int k = 0; k < HEADS; k++) {
        float bk = sbl[k];
        float4 a = make_float4(bk, bk, bk, bk);
#pragma unroll
        for (int h = 0; h < HEADS; h++) {
            const float w = swl[h * HEADS + k];
            a.x = fmaf(l[h].x, w, a.x);
            a.y = fmaf(l[h].y, w, a.y);
            a.z = fmaf(l[h].z, w, a.z);
            a.w = fmaf(l[h].w, w, a.w);
        }
        m1[k] = a;
    }

    float rowmax[HEADS];
#pragma unroll
    for (int k = 0; k < HEADS; k++) {
        float v = fmaxf(fmaxf(m1[k].x, m1[k].y), fmaxf(m1[k].z, m1[k].w));
#pragma unroll
        for (int o = 16; o > 0; o >>= 1) v = fmaxf(v, __shfl_xor_sync(0xffffffff, v, o));
        if (lane == 0) red[k][warp] = v;
    }
    __syncthreads();
#pragma unroll
    for (int k = 0; k < HEADS; k++) {
        float v = red[k][0];
#pragma unroll
        for (int w = 1; w < 8; w++) v = fmaxf(v, red[k][w]);
        rowmax[k] = v;
    }
    __syncthreads();

    float inv[HEADS];
#pragma unroll
    for (int k = 0; k < HEADS; k++) {
        m1[k].x = __expf(m1[k].x - rowmax[k]);
        m1[k].y = __expf(m1[k].y - rowmax[k]);
        m1[k].z = __expf(m1[k].z - rowmax[k]);
        m1[k].w = __expf(m1[k].w - rowmax[k]);
        float s = (m1[k].x + m1[k].y) + (m1[k].z + m1[k].w);
#pragma unroll
        for (int o = 16; o > 0; o >>= 1) s += __shfl_xor_sync(0xffffffff, s, o);
        if (lane == 0) red[k][warp] = s;
    }
    __syncthreads();
#pragma unroll
    for (int k = 0; k < HEADS; k++) {
        float s = red[k][0];
#pragma unroll
        for (int w = 1; w < 8; w++) s += red[k][w];
        inv[k] = 1.0f / s;
    }

#pragma unroll
    for (int h = 0; h < HEADS; h++) {
        m1[h].x *= inv[h]; m1[h].y *= inv[h];
        m1[h].z *= inv[h]; m1[h].w *= inv[h];
    }

    float* ob = attn_out + ((size_t)b * HEADS * SEQ + n) * SEQ + tid * 4;
#pragma unroll
    for (int k = 0; k < HEADS; k++) {
        float bk = sbw[k];
        float4 a = make_float4(bk, bk, bk, bk);
#pragma unroll
        for (int h = 0; h < HEADS; h++) {
            const float w = sww[h * HEADS + k];
            a.x = fmaf(m1[h].x, w, a.x);
            a.y = fmaf(m1[h].y, w, a.y);
            a.z = fmaf(m1[h].z, w, a.z);
            a.w = fmaf(m1[h].w, w, a.w);
        }
        *(float4*)&ob[(size_t)k * SEQ * SEQ] = a;
    }
}

// ---------------------------------------------------------------------------
extern "C" void kernel_launch(void* const* d_in, const int* in_sizes, int n_in,
                              void* d_out, int out_size)
{
    const float* x      = (const float*)d_in[0];
    const float* W_qkv  = (const float*)d_in[1];
    const float* b_qkv  = (const float*)d_in[2];
    const float* W_l    = (const float*)d_in[3];
    const float* b_l    = (const float*)d_in[4];
    const float* W_w    = (const float*)d_in[5];
    const float* b_w    = (const float*)d_in[6];
    const float* W_proj = (const float*)d_in[7];
    const float* b_proj = (const float*)d_in[8];

    float* out  = (float*)d_out;
    float* attn = out + OUT_ELEMS;

    float* logits_p;
    __half *xh, *xl, *qh, *ql, *wqh, *wql, *wph, *wpl, *vh, *vl, *ch, *cl;
    cudaGetSymbolAddress((void**)&logits_p, g_logits);
    cudaGetSymbolAddress((void**)&xh, g_x_hi);      cudaGetSymbolAddress((void**)&xl, g_x_lo);
    cudaGetSymbolAddress((void**)&qh, g_qkv_hi);    cudaGetSymbolAddress((void**)&ql, g_qkv_lo);
    cudaGetSymbolAddress((void**)&wqh, g_wqkvt_hi); cudaGetSymbolAddress((void**)&wql, g_wqkvt_lo);
    cudaGetSymbolAddress((void**)&wph, g_wprojt_hi);cudaGetSymbolAddress((void**)&wpl, g_wprojt_lo);
    cudaGetSymbolAddress((void**)&vh, g_vt_hi);     cudaGetSymbolAddress((void**)&vl, g_vt_lo);
    cudaGetSymbolAddress((void**)&ch, g_ctx_hi);    cudaGetSymbolAddress((void**)&cl, g_ctx_lo);

    const int smem2st = 2 * 49152;   // 98304: two BK=64 stages (BN=64)
    const int smem1st = 49152;       // K2 single chunk
    const int smemK4  = 2 * 32768;   // 65536
    cudaFuncSetAttribute(tc_gemm<0>, cudaFuncAttributeMaxDynamicSharedMemorySize, smem2st);
    cudaFuncSetAttribute(tc_gemm<1>, cudaFuncAttributeMaxDynamicSharedMemorySize, smem1st);
    cudaFuncSetAttribute(tc_gemm<3>, cudaFuncAttributeMaxDynamicSharedMemorySize, smem2st);
    cudaFuncSetAttribute(tc_gemm_av, cudaFuncAttributeMaxDynamicSharedMemorySize, smemK4);

    // P0: presplit x
    presplit<<<(TOKS * CDIM / 4 + 255) / 256, 256>>>(x, xh, xl, TOKS * CDIM / 4);

    // P1/P2: transpose+split weights -> [N][K] fp16 hi/lo
    transpose_split<<<dim3(QKVC / 32, CDIM / 32), dim3(32, 8)>>>(W_qkv, wqh, wql, CDIM, QKVC);
    transpose_split<<<dim3(CDIM / 32, CDIM / 32), dim3(32, 8)>>>(W_proj, wph, wpl, CDIM, CDIM);

    // K1: qkv = x @ W_qkv^T' + b (q scaled) -> qkv_hi/lo
    tc_gemm<0><<<dim3(QKVC / 64, TOKS / 128, 1), 256, smem2st>>>(
        xh, xl, wqh, wql, b_qkv, qh, ql);

    // P3: v transpose -> vt_hi/lo [bh][d][m]
    vt_split<<<dim3(SEQ / 32, HDIM / 32, BATCH * HEADS), dim3(32, 8)>>>(qh, ql, vh, vl);

    // K2: logits = q @ k^T per (b,h)  (fp32 out)
    tc_gemm<1><<<dim3(SEQ / 64, SEQ / 128, BATCH * HEADS), 256, smem1st>>>(
        qh, ql, qh, ql, nullptr, logits_p, nullptr);

    // K3: mix -> softmax -> mix -> attn output (fp32)
    mix_softmax_kernel<<<TOKS, 256>>>(logits_p, W_l, b_l, W_w, b_w, attn);

    // K4: ctx = attn @ vt^T per (b,h) -> ctx_hi/lo
    tc_gemm_av<<<dim3(1, SEQ / 64, BATCH * HEADS), 256, smemK4>>>(
        attn, vh, vl, ch, cl);

    // K5: out = ctx @ W_proj^T' + b (fp32 out)
    tc_gemm<3><<<dim3(CDIM / 64, TOKS / 128, 1), 256, smem2st>>>(
        ch, cl, wph, wpl, b_proj, out, nullptr);
}